// round 1
// baseline (speedup 1.0000x reference)
#include <cuda_runtime.h>
#include <stdint.h>

#define BB 64
#define NN 68
#define ZZ 384
#define MM 46
#define DC 7
#define EE (MM*DC)   /* 322 */
#define NITER 10
#define MAXDEG 46
#define ZT 128

// Iteration-carried per-edge messages, quantized codes k in [-31,31], value = k/16.
__device__ int8_t  g_prev[BB * EE * ZZ];           // ~7.9 MB
// Variable-node totals (xa_in + sum of incident messages), layout [b][n][z]
__device__ float   g_vn[BB * NN * ZZ];             // ~6.7 MB
// CSR: variable -> incident edges
__device__ int     g_var_deg[NN];
__device__ int16_t g_var_edges[NN * MAXDEG];

// ---------------------------------------------------------------------------
// Build var->edge CSR (tiny, deterministic, runs each launch)
// ---------------------------------------------------------------------------
__global__ void setup_csr(const int* __restrict__ etv) {
    int n = threadIdx.x;
    if (n >= NN) return;
    int d = 0;
    for (int e = 0; e < EE; ++e) {
        if (etv[e] == n) {
            g_var_edges[n * MAXDEG + d] = (int16_t)e;
            ++d;
        }
    }
    g_var_deg[n] = d;
}

// ---------------------------------------------------------------------------
// Check-node kernel: one CTA per (check m, batch b), one thread per zc.
// Reads vn at shifted z (coalesced along z), does min-sum over the 7 edges,
// quantizes, writes new message codes into g_prev at the shifted z
// (bijective in z -> race-free).
// ---------------------------------------------------------------------------
template <bool FIRST>
__global__ void __launch_bounds__(ZZ)
check_kernel(const float* __restrict__ vn_in,
             const int*   __restrict__ etv,
             const int*   __restrict__ shift,
             const float* __restrict__ cnw,
             int it) {
    const int m  = blockIdx.x;
    const int b  = blockIdx.y;
    const int zc = threadIdx.x;
    const float w = cnw[it];
    const int base = m * DC;

    const float* __restrict__ vn = FIRST ? vn_in : g_vn;

    int zi[DC];
    int vi[DC];
#pragma unroll
    for (int j = 0; j < DC; ++j) {
        const int e = base + j;
        int z = zc + shift[e];
        if (z >= ZZ) z -= ZZ;
        zi[j] = z;
        vi[j] = etv[e];
    }

    float a[DC];
    unsigned negmask = 0;
    float min1 = 1e30f, min2 = 1e30f;
    int cnt = 0;
#pragma unroll
    for (int j = 0; j < DC; ++j) {
        const int e = base + j;
        float x = vn[(b * NN + vi[j]) * ZZ + zi[j]];
        if (!FIRST) {
            x -= (float)g_prev[(b * EE + e) * ZZ + zi[j]] * 0.0625f;
        }
        // quantize: k = min(rint(|x|*16), 31); value = sign * k/16
        float k = fminf(rintf(fabsf(x) * 16.0f), 31.0f);
        const bool neg = (x < 0.0f) && (k > 0.0f);  // quantized -0 is non-negative
        if (neg) negmask |= (1u << j);
        a[j] = k;
        if (k < min1)        { min2 = min1; min1 = k; cnt = 1; }
        else if (k == min1)  { ++cnt; }
        else if (k < min2)   { min2 = k; }
    }

    const float tot = (__popc(negmask) & 1) ? -1.0f : 1.0f;
#pragma unroll
    for (int j = 0; j < DC; ++j) {
        const int e = base + j;
        const float ext = (cnt == 1 && a[j] == min1) ? min2 : min1;
        const float sgn = ((negmask >> j) & 1u) ? -tot : tot;
        // Q(w * sgn * ext/16): magnitude code = min(rint(w*ext), 31)
        const float qk = fminf(rintf(w * ext), 31.0f);
        g_prev[(b * EE + e) * ZZ + zi[j]] = (int8_t)(sgn * qk);
    }
}

// ---------------------------------------------------------------------------
// Variable-node kernel: CTA per (z-tile, batch). Sums incident message codes
// in INTEGER (exact), adds xa once (matches reference rounding), writes the
// output slice (transposed via smem for coalescing) and the vn scratch.
// ---------------------------------------------------------------------------
__global__ void __launch_bounds__(ZT)
var_kernel(const float* __restrict__ xa,
           float* __restrict__ out_slice,
           int write_vn) {
    const int b  = blockIdx.y;
    const int z0 = blockIdx.x * ZT;
    const int tz = threadIdx.x;
    const int z  = z0 + tz;

    __shared__ float tile[NN][ZT + 1];

    for (int n = 0; n < NN; ++n) {
        const int d = g_var_deg[n];
        const int16_t* __restrict__ el = &g_var_edges[n * MAXDEG];
        int acc = 0;
        for (int i = 0; i < d; ++i) {
            const int e = el[i];
            acc += (int)g_prev[(b * EE + e) * ZZ + z];
        }
        const float s = xa[(b * NN + n) * ZZ + z] + (float)acc * 0.0625f;
        if (write_vn) g_vn[(b * NN + n) * ZZ + z] = s;
        tile[n][tz] = s;
    }
    __syncthreads();

    // out layout [b][z][n]: write with n fastest for coalescing
    float* __restrict__ op = out_slice + (size_t)(b * ZZ + z0) * NN;
    for (int idx = threadIdx.x; idx < NN * ZT; idx += ZT) {
        const int zl = idx / NN;
        const int n  = idx - zl * NN;
        op[idx] = tile[n][zl];
    }
}

// ---------------------------------------------------------------------------
// Launch
// ---------------------------------------------------------------------------
extern "C" void kernel_launch(void* const* d_in, const int* in_sizes, int n_in,
                              void* d_out, int out_size) {
    const float* xa    = (const float*)d_in[0];   // (B, N, Z) f32
    const float* cnw   = (const float*)d_in[1];   // (ITERS,) f32
    const int*   etv   = (const int*)d_in[2];     // (E,) i32
    // d_in[3] = edge_to_check (repeat(arange(M), 7)) — grouping is implicit
    const int*   shift = (const int*)d_in[4];     // (E,) i32
    float* out = (float*)d_out;                   // (ITERS, B, Z, N) f32

    setup_csr<<<1, NN>>>(etv);

    const dim3 cgrid(MM, BB);
    const dim3 vgrid(ZZ / ZT, BB);
    const size_t slice = (size_t)BB * ZZ * NN;

    for (int it = 0; it < NITER; ++it) {
        if (it == 0)
            check_kernel<true><<<cgrid, ZZ>>>(xa, etv, shift, cnw, it);
        else
            check_kernel<false><<<cgrid, ZZ>>>(nullptr, etv, shift, cnw, it);
        var_kernel<<<vgrid, ZT>>>(xa, out + (size_t)it * slice,
                                  (it < NITER - 1) ? 1 : 0);
    }
}

// round 2
// speedup vs baseline: 3.2094x; 3.2094x over previous
#include <cuda_runtime.h>
#include <stdint.h>

#define BB 64
#define NN 68
#define ZZ 384
#define MM 46
#define DC 7
#define EE (MM*DC)   /* 322 */
#define NITER 10
#define MAXDEG 46

// Iteration-carried per-edge messages, quantized codes k in [-31,31], value = k/16.
__device__ int8_t  g_prev[BB * EE * ZZ];           // ~7.9 MB
// Variable-node totals (xa_in + sum of incident messages), layout [b][n][z]
__device__ float   g_vn[BB * NN * ZZ];             // ~6.7 MB
// CSR: variable -> incident edges
__device__ int     g_var_deg[NN];
__device__ int16_t g_var_edges[NN * MAXDEG];

// ---------------------------------------------------------------------------
// Build var->edge CSR via atomic scatter. Slot order is nondeterministic but
// the var-node accumulation is an exact integer sum (commutative), so the
// final output is bit-identical regardless of order.
// ---------------------------------------------------------------------------
__global__ void setup_csr(const int* __restrict__ etv) {
    const int t = threadIdx.x;
    if (t < NN) g_var_deg[t] = 0;
    __syncthreads();
    if (t < EE) {
        const int n = etv[t];
        const int slot = atomicAdd(&g_var_deg[n], 1);
        g_var_edges[n * MAXDEG + slot] = (int16_t)t;
    }
}

// ---------------------------------------------------------------------------
// Check-node kernel: one CTA per (check m, batch b), one thread per zc.
// ---------------------------------------------------------------------------
template <bool FIRST>
__global__ void __launch_bounds__(ZZ)
check_kernel(const float* __restrict__ vn_in,
             const int*   __restrict__ etv,
             const int*   __restrict__ shift,
             const float* __restrict__ cnw,
             int it) {
    const int m  = blockIdx.x;
    const int b  = blockIdx.y;
    const int zc = threadIdx.x;
    const float w = cnw[it];
    const int base = m * DC;

    const float* __restrict__ vn = FIRST ? vn_in : g_vn;

    int zi[DC];
    int vi[DC];
#pragma unroll
    for (int j = 0; j < DC; ++j) {
        const int e = base + j;
        int z = zc + shift[e];
        if (z >= ZZ) z -= ZZ;
        zi[j] = z;
        vi[j] = etv[e];
    }

    float a[DC];
    unsigned negmask = 0;
    float min1 = 1e30f, min2 = 1e30f;
    int cnt = 0;
#pragma unroll
    for (int j = 0; j < DC; ++j) {
        const int e = base + j;
        float x = vn[(b * NN + vi[j]) * ZZ + zi[j]];
        if (!FIRST) {
            x -= (float)g_prev[(b * EE + e) * ZZ + zi[j]] * 0.0625f;
        }
        float k = fminf(rintf(fabsf(x) * 16.0f), 31.0f);
        const bool neg = (x < 0.0f) && (k > 0.0f);  // quantized -0 is non-negative
        if (neg) negmask |= (1u << j);
        a[j] = k;
        if (k < min1)        { min2 = min1; min1 = k; cnt = 1; }
        else if (k == min1)  { ++cnt; }
        else if (k < min2)   { min2 = k; }
    }

    const float tot = (__popc(negmask) & 1) ? -1.0f : 1.0f;
#pragma unroll
    for (int j = 0; j < DC; ++j) {
        const int e = base + j;
        const float ext = (cnt == 1 && a[j] == min1) ? min2 : min1;
        const float sgn = ((negmask >> j) & 1u) ? -tot : tot;
        const float qk = fminf(rintf(w * ext), 31.0f);
        g_prev[(b * EE + e) * ZZ + zi[j]] = (int8_t)(sgn * qk);
    }
}

// ---------------------------------------------------------------------------
// Variable-node kernel: CTA per (32-z tile, batch). Block = 32 z-lanes x 8
// n-groups = 256 threads. Integer-exact message sum, adds xa once, writes
// the vn scratch (z-coalesced) and the output slice (n-fastest via smem
// transpose, conflict-free).
// ---------------------------------------------------------------------------
#define VZT 32
#define VNG 8
__global__ void __launch_bounds__(VZT * VNG)
var_kernel(const float* __restrict__ xa,
           float* __restrict__ out_slice,
           int write_vn) {
    const int b  = blockIdx.y;
    const int z0 = blockIdx.x * VZT;
    const int tx = threadIdx.x & (VZT - 1);   // z lane
    const int ty = threadIdx.x >> 5;          // n group
    const int z  = z0 + tx;

    __shared__ float tile[NN][VZT + 1];

    for (int n = ty; n < NN; n += VNG) {
        const int d = g_var_deg[n];
        const int16_t* __restrict__ el = &g_var_edges[n * MAXDEG];
        int acc = 0;
        for (int i = 0; i < d; ++i) {
            const int e = el[i];                 // uniform across warp -> broadcast
            acc += (int)g_prev[(b * EE + e) * ZZ + z];
        }
        const float s = xa[(b * NN + n) * ZZ + z] + (float)acc * 0.0625f;
        if (write_vn) g_vn[(b * NN + n) * ZZ + z] = s;
        tile[n][tx] = s;
    }
    __syncthreads();

    // out layout [b][z][n]: n fastest, coalesced
    float* __restrict__ op = out_slice + (size_t)(b * ZZ + z0) * NN;
    for (int idx = threadIdx.x; idx < NN * VZT; idx += VZT * VNG) {
        const int zl = idx / NN;
        const int n  = idx - zl * NN;
        op[idx] = tile[n][zl];
    }
}

// ---------------------------------------------------------------------------
// Launch
// ---------------------------------------------------------------------------
extern "C" void kernel_launch(void* const* d_in, const int* in_sizes, int n_in,
                              void* d_out, int out_size) {
    const float* xa    = (const float*)d_in[0];   // (B, N, Z) f32
    const float* cnw   = (const float*)d_in[1];   // (ITERS,) f32
    const int*   etv   = (const int*)d_in[2];     // (E,) i32
    // d_in[3] = edge_to_check (repeat(arange(M), 7)) — grouping is implicit
    const int*   shift = (const int*)d_in[4];     // (E,) i32
    float* out = (float*)d_out;                   // (ITERS, B, Z, N) f32

    setup_csr<<<1, EE>>>(etv);

    const dim3 cgrid(MM, BB);
    const dim3 vgrid(ZZ / VZT, BB);
    const size_t slice = (size_t)BB * ZZ * NN;

    for (int it = 0; it < NITER; ++it) {
        if (it == 0)
            check_kernel<true><<<cgrid, ZZ>>>(xa, etv, shift, cnw, it);
        else
            check_kernel<false><<<cgrid, ZZ>>>(nullptr, etv, shift, cnw, it);
        var_kernel<<<vgrid, VZT * VNG>>>(xa, out + (size_t)it * slice,
                                         (it < NITER - 1) ? 1 : 0);
    }
}

// round 3
// speedup vs baseline: 3.2328x; 1.0073x over previous
#include <cuda_runtime.h>
#include <stdint.h>

#define BB 64
#define NN 68
#define ZZ 384
#define MM 46
#define DC 7
#define EE (MM*DC)   /* 322 */
#define NITER 10
#define MAXDEG 46

#define ZQ 4          /* z elements per check thread */
#define CT 96         /* ZZ / ZQ */
#define CM 2          /* checks per CTA */

// Iteration-carried per-edge messages in CHECK-ALIGNED layout:
// g_prev[b][e][zc] = msg code produced by check row zc (value = code/16).
__device__ int8_t  g_prev[BB * EE * ZZ];           // ~7.9 MB
// Variable-node totals (xa_in + sum of incident messages), layout [b][n][z]
__device__ float   g_vn[BB * NN * ZZ];             // ~6.7 MB
// CSR: variable -> incident edges (+ per-slot shift and e*ZZ offset)
__device__ int     g_var_deg[NN];
__device__ int     g_var_off[NN * MAXDEG];         // e * ZZ
__device__ int16_t g_var_shift[NN * MAXDEG];       // shift[e]

// ---------------------------------------------------------------------------
// Build var->edge CSR via atomic scatter. Slot order nondeterministic but the
// var-node accumulation is an exact integer sum (commutative) -> bit-identical.
// ---------------------------------------------------------------------------
__global__ void setup_csr(const int* __restrict__ etv,
                          const int* __restrict__ shift) {
    const int t = threadIdx.x;
    if (t < NN) g_var_deg[t] = 0;
    __syncthreads();
    if (t < EE) {
        const int n = etv[t];
        const int slot = atomicAdd(&g_var_deg[n], 1);
        g_var_off[n * MAXDEG + slot]   = t * ZZ;
        g_var_shift[n * MAXDEG + slot] = (int16_t)shift[t];
    }
}

// ---------------------------------------------------------------------------
// Check-node kernel. CTA = CM checks x one batch; 96 threads per check, each
// handling 4 z rows strided by 96. prev is check-aligned -> constant-offset
// access from one base pointer. vn gathered at zi = zc + shift (coalesced).
// ---------------------------------------------------------------------------
template <bool FIRST>
__global__ void __launch_bounds__(CT * CM)
check_kernel(const float* __restrict__ vn_in,
             const int*   __restrict__ etv,
             const int*   __restrict__ shift,
             const float* __restrict__ cnw,
             int it) {
    const int m = blockIdx.x * CM + threadIdx.y;
    const int b = blockIdx.y;
    const int t = threadIdx.x;
    const float w = cnw[it];
    const int base = m * DC;

    const float* __restrict__ vn = FIRST ? vn_in : g_vn;
    // prev base for this (b, m, t): element (j, k) lives at pb[j*ZZ + k*CT]
    int8_t* __restrict__ pb = g_prev + (b * EE + base) * ZZ + t;

    int zi[DC];     // current z row per edge (in variable space)
    int vb[DC];     // vn row offset per edge
#pragma unroll
    for (int j = 0; j < DC; ++j) {
        const int e = base + j;
        int z = t + shift[e];
        if (z >= ZZ) z -= ZZ;
        zi[j] = z;
        vb[j] = (b * NN + etv[e]) * ZZ;
    }

#pragma unroll
    for (int k = 0; k < ZQ; ++k) {
        float a[DC];
        unsigned negmask = 0;
        float min1 = 1e30f, min2 = 1e30f;
        int cnt = 0;
#pragma unroll
        for (int j = 0; j < DC; ++j) {
            float x = __ldg(vn + vb[j] + zi[j]);
            if (!FIRST) x -= (float)pb[j * ZZ + k * CT] * 0.0625f;
            const float kk = fminf(rintf(fabsf(x) * 16.0f), 31.0f);
            const bool neg = (x < 0.0f) && (kk > 0.0f);  // quantized -0 is non-negative
            if (neg) negmask |= (1u << j);
            a[j] = kk;
            if (kk < min1)       { min2 = min1; min1 = kk; cnt = 1; }
            else if (kk == min1) { ++cnt; }
            else if (kk < min2)  { min2 = kk; }
        }

        const float q1 = fminf(rintf(w * min1), 31.0f);
        const float q2 = fminf(rintf(w * min2), 31.0f);
        const bool unique = (cnt == 1);
        const float tot = (__popc(negmask) & 1) ? -1.0f : 1.0f;
#pragma unroll
        for (int j = 0; j < DC; ++j) {
            const float q   = (unique && a[j] == min1) ? q2 : q1;
            const float sgn = ((negmask >> j) & 1u) ? -tot : tot;
            pb[j * ZZ + k * CT] = (int8_t)(sgn * q);
        }

        if (k < ZQ - 1) {
#pragma unroll
            for (int j = 0; j < DC; ++j) {
                zi[j] += CT;
                if (zi[j] >= ZZ) zi[j] -= ZZ;
            }
        }
    }
}

// ---------------------------------------------------------------------------
// Variable-node kernel: CTA per (32-z tile, batch), 32 z-lanes x 8 n-groups.
// prev is check-aligned, so each edge read applies its shift: zi = z - s.
// Integer-exact message sum; adds xa once; writes vn scratch + output slice.
// ---------------------------------------------------------------------------
#define VZT 32
#define VNG 8
__global__ void __launch_bounds__(VZT * VNG)
var_kernel(const float* __restrict__ xa,
           float* __restrict__ out_slice,
           int write_vn) {
    const int b  = blockIdx.y;
    const int z0 = blockIdx.x * VZT;
    const int tx = threadIdx.x & (VZT - 1);   // z lane
    const int ty = threadIdx.x >> 5;          // n group
    const int z  = z0 + tx;
    const int bbase = b * EE * ZZ;

    __shared__ float tile[NN][VZT + 1];

    for (int n = ty; n < NN; n += VNG) {
        const int d = g_var_deg[n];
        const int*     __restrict__ ol = &g_var_off[n * MAXDEG];
        const int16_t* __restrict__ sl = &g_var_shift[n * MAXDEG];
        int acc = 0;
        for (int i = 0; i < d; ++i) {
            int zi = z - (int)sl[i];
            if (zi < 0) zi += ZZ;
            acc += (int)g_prev[bbase + ol[i] + zi];
        }
        const float s = xa[(b * NN + n) * ZZ + z] + (float)acc * 0.0625f;
        if (write_vn) g_vn[(b * NN + n) * ZZ + z] = s;
        tile[n][tx] = s;
    }
    __syncthreads();

    // out layout [b][z][n]: n fastest, coalesced
    float* __restrict__ op = out_slice + (size_t)(b * ZZ + z0) * NN;
    for (int idx = threadIdx.x; idx < NN * VZT; idx += VZT * VNG) {
        const int zl = idx / NN;
        const int n  = idx - zl * NN;
        op[idx] = tile[n][zl];
    }
}

// ---------------------------------------------------------------------------
// Launch
// ---------------------------------------------------------------------------
extern "C" void kernel_launch(void* const* d_in, const int* in_sizes, int n_in,
                              void* d_out, int out_size) {
    const float* xa    = (const float*)d_in[0];   // (B, N, Z) f32
    const float* cnw   = (const float*)d_in[1];   // (ITERS,) f32
    const int*   etv   = (const int*)d_in[2];     // (E,) i32
    // d_in[3] = edge_to_check (repeat(arange(M), 7)) — grouping is implicit
    const int*   shift = (const int*)d_in[4];     // (E,) i32
    float* out = (float*)d_out;                   // (ITERS, B, Z, N) f32

    setup_csr<<<1, EE>>>(etv, shift);

    const dim3 cgrid(MM / CM, BB);
    const dim3 cblock(CT, CM);
    const dim3 vgrid(ZZ / VZT, BB);
    const size_t slice = (size_t)BB * ZZ * NN;

    for (int it = 0; it < NITER; ++it) {
        if (it == 0)
            check_kernel<true><<<cgrid, cblock>>>(xa, etv, shift, cnw, it);
        else
            check_kernel<false><<<cgrid, cblock>>>(nullptr, etv, shift, cnw, it);
        var_kernel<<<vgrid, VZT * VNG>>>(xa, out + (size_t)it * slice,
                                         (it < NITER - 1) ? 1 : 0);
    }
}